// round 8
// baseline (speedup 1.0000x reference)
#include <cuda_runtime.h>

#define TT 100
#define BB 16384
#define IN 6
#define EH 8
#define SH 24
#define CH 16
#define NC 3
#define RH 16

// Weights in shared memory; every row 16B-aligned for float4 LDS broadcast.
struct Smem {
    float Wec[EH][8];       // padded 6 -> 8 (zeros)
    float Wer[EH][8];
    float Ws [SH][2 * EH];  // 16 floats/row
    float Wch[CH][SH];      // 24 floats/row
    float Wrh[RH][SH];
    float Wco[NC][CH];      // 16 floats/row
    float Wro[RH];
    float bec[EH], ber[EH], bs[SH], bch[CH], bco[NC], brh[RH], bro;
};

// bit i of m -> exact 0.0f / 1.0f
__device__ __forceinline__ float bit2f(unsigned m, int i) {
    return __int_as_float((((int)(m << (31 - i))) >> 31) & 0x3F800000);
}

// snntorch Leaky, reset='subtract', THR=1, BETA=0.9 — bit-exact vs reference.
__device__ __forceinline__ float lif(float cur, float& m, unsigned& mask, unsigned bit) {
    float mold = m;
    m = fmaf(0.9f, m, cur);
    if (mold > 1.0f) m -= 1.0f;
    bool sp = (m > 1.0f);
    if (sp) mask |= bit;
    return sp ? 1.0f : 0.0f;
}

__global__ void __launch_bounds__(512)
snn_kernel(const float* __restrict__ x,
           const float* __restrict__ We_c, const float* __restrict__ be_c,
           const float* __restrict__ We_r, const float* __restrict__ be_r,
           const float* __restrict__ Wsp,  const float* __restrict__ bsp,
           const float* __restrict__ Wchp, const float* __restrict__ bchp,
           const float* __restrict__ Wcop, const float* __restrict__ bcop,
           const float* __restrict__ Wrhp, const float* __restrict__ brhp,
           const float* __restrict__ Wrop, const float* __restrict__ brop,
           float* __restrict__ out)
{
    __shared__ __align__(16) Smem sm;
    const int tid = threadIdx.x;

    // ---- cooperative weight staging ----
    for (int idx = tid; idx < EH * 8; idx += 512) {
        int o = idx / 8, i = idx % 8;
        sm.Wec[o][i] = (i < IN) ? We_c[o * IN + i] : 0.f;
        sm.Wer[o][i] = (i < IN) ? We_r[o * IN + i] : 0.f;
    }
    for (int idx = tid; idx < SH * 2 * EH; idx += 512) ((float*)sm.Ws)[idx]  = Wsp[idx];
    for (int idx = tid; idx < CH * SH;     idx += 512) ((float*)sm.Wch)[idx] = Wchp[idx];
    for (int idx = tid; idx < RH * SH;     idx += 512) ((float*)sm.Wrh)[idx] = Wrhp[idx];
    for (int idx = tid; idx < NC * CH;     idx += 512) ((float*)sm.Wco)[idx] = Wcop[idx];
    if (tid < RH) { sm.Wro[tid] = Wrop[tid]; sm.brh[tid] = brhp[tid]; }
    if (tid < EH) { sm.bec[tid] = be_c[tid]; sm.ber[tid] = be_r[tid]; }
    if (tid < SH) sm.bs[tid]  = bsp[tid];
    if (tid < CH) sm.bch[tid] = bchp[tid];
    if (tid < NC) sm.bco[tid] = bcop[tid];
    if (tid == 0) sm.bro = brop[0];
    __syncthreads();

    // ---- 4-way split: lanes {l, l^8, l^16, l^24} share one element ----
    const int lane = tid & 31;
    const int warp = tid >> 5;
    const int role = lane >> 3;           // 0..3
    const int sub  = lane & 7;
    const int e    = blockIdx.x * 128 + warp * 8 + sub;

    const int eo = role * 2;              // encoder rows (ec and er)
    const int so = role * 6;              // shared rows
    const int ho = role * 4;              // ch / rh rows

    // ---- hoist biases & tail row into registers ----
    float b_ec[2], b_er[2], b_sh[6], b_ch[4], b_rh[4];
#pragma unroll
    for (int k = 0; k < 2; ++k) { b_ec[k] = sm.bec[eo + k]; b_er[k] = sm.ber[eo + k]; }
#pragma unroll
    for (int k = 0; k < 6; ++k) b_sh[k] = sm.bs[so + k];
#pragma unroll
    for (int k = 0; k < 4; ++k) { b_ch[k] = sm.bch[ho + k]; b_rh[k] = sm.brh[ho + k]; }
    const float4* const wtail = (const float4*)((role < 3) ? sm.Wco[role] : sm.Wro);
    const float btail = (role < 3) ? sm.bco[role] : sm.bro;

    // membranes (this thread's quarter)
    float m_ec[2], m_er[2], m_sh[6], m_ch[4], m_rh[4], m_tail = 0.f;
#pragma unroll
    for (int i = 0; i < 2; ++i) { m_ec[i] = 0.f; m_er[i] = 0.f; }
#pragma unroll
    for (int i = 0; i < 6; ++i) m_sh[i] = 0.f;
#pragma unroll
    for (int i = 0; i < 4; ++i) { m_ch[i] = 0.f; m_rh[i] = 0.f; }

    const size_t TB = (size_t)TT * BB;
    float* const p_mco = out;
    float* const p_sch = out + TB * 3;
    float* const p_mro = out + TB * 19;
    float* const p_srh = out + TB * 20;
    float* const p_ssh = out + TB * 36;
    float* const p_sec = out + TB * 60;
    float* const p_ser = out + TB * 68;

#pragma unroll 1
    for (int t = 0; t < TT; ++t) {
        const size_t r = (size_t)t * BB + e;

        const float2* xp = (const float2*)(x + r * IN);
        const float2 a0 = xp[0], a1 = xp[1], a2 = xp[2];
        // padded to 8 with exact zeros (fmaf(0,0,acc) == acc; acc never -0 here)
        const float xv[8] = {a0.x, a0.y, a1.x, a1.y, a2.x, a2.y, 0.f, 0.f};

        // ---- encoders: 2 ec rows + 2 er rows per thread ----
        unsigned emask = 0;
#pragma unroll
        for (int k = 0; k < 2; ++k) {
            const int o = eo + k;
            const float4* wr = (const float4*)sm.Wec[o];
            float acc = 0.f;
#pragma unroll
            for (int j = 0; j < 2; ++j) {
                const float4 w = wr[j];
                acc = fmaf(xv[4 * j + 0], w.x, acc);
                acc = fmaf(xv[4 * j + 1], w.y, acc);
                acc = fmaf(xv[4 * j + 2], w.z, acc);
                acc = fmaf(xv[4 * j + 3], w.w, acc);
            }
            lif(acc + b_ec[k], m_ec[k], emask, 1u << o);
        }
#pragma unroll
        for (int k = 0; k < 2; ++k) {
            const int o = eo + k;
            const float4* wr = (const float4*)sm.Wer[o];
            float acc = 0.f;
#pragma unroll
            for (int j = 0; j < 2; ++j) {
                const float4 w = wr[j];
                acc = fmaf(xv[4 * j + 0], w.x, acc);
                acc = fmaf(xv[4 * j + 1], w.y, acc);
                acc = fmaf(xv[4 * j + 2], w.z, acc);
                acc = fmaf(xv[4 * j + 3], w.w, acc);
            }
            lif(acc + b_er[k], m_er[k], emask, 1u << (8 + o));
        }
        unsigned efull = emask | __shfl_xor_sync(0xFFFFFFFFu, emask, 8);
        efull |= __shfl_xor_sync(0xFFFFFFFFu, efull, 16);

        float ein[2 * EH];
#pragma unroll
        for (int i = 0; i < 2 * EH; ++i) ein[i] = bit2f(efull, i);

        // ---- shared layer: 6 rows, ascending i (bit-exact) ----
        unsigned shmask = 0;
#pragma unroll
        for (int k = 0; k < 6; ++k) {
            const int o = so + k;
            const float4* wr = (const float4*)sm.Ws[o];
            float acc = 0.f;
#pragma unroll
            for (int j = 0; j < 4; ++j) {
                const float4 w = wr[j];
                acc = fmaf(ein[4 * j + 0], w.x, acc);
                acc = fmaf(ein[4 * j + 1], w.y, acc);
                acc = fmaf(ein[4 * j + 2], w.z, acc);
                acc = fmaf(ein[4 * j + 3], w.w, acc);
            }
            lif(acc + b_sh[k], m_sh[k], shmask, 1u << o);
        }
        unsigned shfull = shmask | __shfl_xor_sync(0xFFFFFFFFu, shmask, 8);
        shfull |= __shfl_xor_sync(0xFFFFFFFFu, shfull, 16);

        float shin[SH];
#pragma unroll
        for (int i = 0; i < SH; ++i) shin[i] = bit2f(shfull, i);

        // ---- classification hidden: 4 rows ----
        float s_ch[4];
        unsigned chmask = 0;
#pragma unroll
        for (int k = 0; k < 4; ++k) {
            const int o = ho + k;
            const float4* wr = (const float4*)sm.Wch[o];
            float acc = 0.f;
#pragma unroll
            for (int j = 0; j < 6; ++j) {
                const float4 w = wr[j];
                acc = fmaf(shin[4 * j + 0], w.x, acc);
                acc = fmaf(shin[4 * j + 1], w.y, acc);
                acc = fmaf(shin[4 * j + 2], w.z, acc);
                acc = fmaf(shin[4 * j + 3], w.w, acc);
            }
            s_ch[k] = lif(acc + b_ch[k], m_ch[k], chmask, 1u << o);
        }
        unsigned chfull = chmask | __shfl_xor_sync(0xFFFFFFFFu, chmask, 8);
        chfull |= __shfl_xor_sync(0xFFFFFFFFu, chfull, 16);

        // ---- regression hidden: 4 rows, butterfly tree (values bit-exact;
        //      the 8 pad-zero adds are skipped — can only change -0 -> +0 on
        //      non-output intermediates, never a spike or stored value) ----
        float s_rh[4];
        unsigned rhmask = 0;
#pragma unroll
        for (int k = 0; k < 4; ++k) {
            const int o = ho + k;
            const float4* wr = (const float4*)sm.Wrh[o];
            float p[SH];
#pragma unroll
            for (int j = 0; j < 6; ++j) {
                const float4 w = wr[j];
                p[4 * j + 0] = shin[4 * j + 0] * w.x;
                p[4 * j + 1] = shin[4 * j + 1] * w.y;
                p[4 * j + 2] = shin[4 * j + 2] * w.z;
                p[4 * j + 3] = shin[4 * j + 3] * w.w;
            }
            // stride 16 (only lanes with a real partner), then 8,4,2,1
#pragma unroll
            for (int i = 0; i < 8; ++i) p[i] = p[i] + p[i + 16];
#pragma unroll
            for (int i = 0; i < 8; ++i) p[i] = p[i] + p[i + 8];
#pragma unroll
            for (int i = 0; i < 4; ++i) p[i] = p[i] + p[i + 4];
#pragma unroll
            for (int i = 0; i < 2; ++i) p[i] = p[i] + p[i + 2];
            p[0] = p[0] + p[1];
            s_rh[k] = lif(p[0] + b_rh[k], m_rh[k], rhmask, 1u << o);
        }
        unsigned rhfull = rhmask | __shfl_xor_sync(0xFFFFFFFFu, rhmask, 8);
        rhfull |= __shfl_xor_sync(0xFFFFFFFFu, rhfull, 16);

        // ---- output tail: roles 0-2 -> Wco rows 0-2, role 3 -> Wro (uniform shape) ----
        {
            const unsigned tmask = (role < 3) ? chfull : rhfull;
            float acc = 0.f;
#pragma unroll
            for (int j = 0; j < 4; ++j) {
                const float4 w = wtail[j];
                acc = fmaf(bit2f(tmask, 4 * j + 0), w.x, acc);
                acc = fmaf(bit2f(tmask, 4 * j + 1), w.y, acc);
                acc = fmaf(bit2f(tmask, 4 * j + 2), w.z, acc);
                acc = fmaf(bit2f(tmask, 4 * j + 3), w.w, acc);
            }
            unsigned du = 0;
            lif(acc + btail, m_tail, du, 0u);
        }

        // ---- stores ----
        if (role < 3) p_mco[r * 3 + role] = m_tail;
        else          p_mro[r] = m_tail;
        {
            float4* q = (float4*)(p_sch + r * 16 + ho);
            q[0] = make_float4(s_ch[0], s_ch[1], s_ch[2], s_ch[3]);
        }
        {
            float4* q = (float4*)(p_srh + r * 16 + ho);
            q[0] = make_float4(s_rh[0], s_rh[1], s_rh[2], s_rh[3]);
        }
        {
            float2* q = (float2*)(p_ssh + r * 24 + so);
            q[0] = make_float2(shin[so + 0], shin[so + 1]);
            q[1] = make_float2(shin[so + 2], shin[so + 3]);
            q[2] = make_float2(shin[so + 4], shin[so + 5]);
        }
        {
            float2* q = (float2*)(p_sec + r * 8 + eo);
            q[0] = make_float2(ein[eo], ein[eo + 1]);
        }
        {
            float2* q = (float2*)(p_ser + r * 8 + eo);
            q[0] = make_float2(ein[8 + eo], ein[8 + eo + 1]);
        }
    }
}

extern "C" void kernel_launch(void* const* d_in, const int* in_sizes, int n_in,
                              void* d_out, int out_size)
{
    snn_kernel<<<128, 512>>>(
        (const float*)d_in[0],
        (const float*)d_in[1],  (const float*)d_in[2],
        (const float*)d_in[3],  (const float*)d_in[4],
        (const float*)d_in[5],  (const float*)d_in[6],
        (const float*)d_in[7],  (const float*)d_in[8],
        (const float*)d_in[9],  (const float*)d_in[10],
        (const float*)d_in[11], (const float*)d_in[12],
        (const float*)d_in[13], (const float*)d_in[14],
        (float*)d_out);
}

// round 10
// speedup vs baseline: 1.4587x; 1.4587x over previous
#include <cuda_runtime.h>

#define TT 100
#define BB 16384

// Interleaved weights: index [k][j][role] so the 4 roles of a warp read 4
// CONSECUTIVE float4s in one LDS.128 -> conflict-free by construction.
// sp: per-element spike buffer, row stride 76 floats (304B) -> element lanes
// map to distinct bank groups (12*e mod 32) -> conflict-free float4 access.
// Layout per element row: ec[0:8) er[8:16) sh[16:40) ch[40:56) rh[56:72)
struct Smem {
    float4 ecI[2][2][4];   // enc-class: rows 2*role+k, cols 4j..4j+3 (padded 6->8)
    float4 erI[2][2][4];   // enc-reg
    float4 sI [6][4][4];   // shared:    rows 6*role+k
    float4 chI[4][6][4];   // cls hidden rows 4*role+k
    float4 rhI[4][6][4];   // reg hidden rows 4*role+k
    float4 tI [4][4];      // tail: roles 0-2 -> Wco row, role 3 -> Wro
    float  sp[128][76];
    float  bec[8], ber[8], bs[24], bch[16], bco[3], brh[16], bro[1];
};

// snntorch Leaky, reset='subtract', THR=1, BETA=0.9 — bit-exact vs reference.
__device__ __forceinline__ float lif(float cur, float& m) {
    float mold = m;
    m = fmaf(0.9f, m, cur);
    if (mold > 1.0f) m -= 1.0f;
    return (m > 1.0f) ? 1.0f : 0.0f;
}

__global__ void __launch_bounds__(512)
snn_kernel(const float* __restrict__ x,
           const float* __restrict__ We_c, const float* __restrict__ be_c,
           const float* __restrict__ We_r, const float* __restrict__ be_r,
           const float* __restrict__ Wsp,  const float* __restrict__ bsp,
           const float* __restrict__ Wchp, const float* __restrict__ bchp,
           const float* __restrict__ Wcop, const float* __restrict__ bcop,
           const float* __restrict__ Wrhp, const float* __restrict__ brhp,
           const float* __restrict__ Wrop, const float* __restrict__ brop,
           float* __restrict__ out)
{
    __shared__ __align__(16) Smem sm;
    const int tid = threadIdx.x;

    // ---- staging: permute weights into interleaved layout ----
    for (int idx = tid; idx < 64; idx += 512) {          // ecI / erI
        int c = idx & 3, role = (idx >> 2) & 3, j = (idx >> 4) & 1, k = idx >> 5;
        int col = 4 * j + c, row = 2 * role + k;
        ((float*)sm.ecI)[idx] = (col < 6) ? We_c[row * 6 + col] : 0.f;
        ((float*)sm.erI)[idx] = (col < 6) ? We_r[row * 6 + col] : 0.f;
    }
    for (int idx = tid; idx < 384; idx += 512) {         // sI
        int c = idx & 3, role = (idx >> 2) & 3, j = (idx >> 4) & 3, k = idx >> 6;
        ((float*)sm.sI)[idx] = Wsp[(6 * role + k) * 16 + 4 * j + c];
    }
    for (int idx = tid; idx < 384; idx += 512) {         // chI / rhI
        int c = idx & 3, role = (idx >> 2) & 3, jk = idx >> 4;
        int j = jk % 6, k = jk / 6, off = (4 * role + k) * 24 + 4 * j + c;
        ((float*)sm.chI)[idx] = Wchp[off];
        ((float*)sm.rhI)[idx] = Wrhp[off];
    }
    for (int idx = tid; idx < 64; idx += 512) {          // tI
        int c = idx & 3, role = (idx >> 2) & 3, j = idx >> 4;
        ((float*)sm.tI)[idx] = (role < 3) ? Wcop[role * 16 + 4 * j + c]
                                          : Wrop[4 * j + c];
    }
    if (tid < 8)  { sm.bec[tid] = be_c[tid]; sm.ber[tid] = be_r[tid]; }
    if (tid < 24) sm.bs[tid]  = bsp[tid];
    if (tid < 16) { sm.bch[tid] = bchp[tid]; sm.brh[tid] = brhp[tid]; }
    if (tid < 3)  sm.bco[tid] = bcop[tid];
    if (tid == 0) sm.bro[0] = brop[0];
    __syncthreads();

    // ---- 4-way split: lanes {l, l^8, l^16, l^24} share one element ----
    const int lane = tid & 31;
    const int warp = tid >> 5;
    const int role = lane >> 3;          // 0..3
    const int sub  = lane & 7;
    const int elem = warp * 8 + sub;     // element within block (0..127)
    const int e    = blockIdx.x * 128 + elem;

    const int eo = role * 2;             // encoder row base (ec and er)
    const int so = role * 6;             // shared row base
    const int ho = role * 4;             // ch / rh row base

    float* const sb = &sm.sp[elem][0];   // this element's spike buffer

    // biases -> registers
    float b_ec[2], b_er[2], b_sh[6], b_ch[4], b_rh[4];
#pragma unroll
    for (int k = 0; k < 2; ++k) { b_ec[k] = sm.bec[eo + k]; b_er[k] = sm.ber[eo + k]; }
#pragma unroll
    for (int k = 0; k < 6; ++k) b_sh[k] = sm.bs[so + k];
#pragma unroll
    for (int k = 0; k < 4; ++k) { b_ch[k] = sm.bch[ho + k]; b_rh[k] = sm.brh[ho + k]; }
    const float btail = (role < 3) ? sm.bco[role] : sm.bro[0];
    const float4* const tin = (const float4*)(sb + ((role < 3) ? 40 : 56));

    // membranes
    float m_ec[2], m_er[2], m_sh[6], m_ch[4], m_rh[4], m_tail = 0.f;
#pragma unroll
    for (int i = 0; i < 2; ++i) { m_ec[i] = 0.f; m_er[i] = 0.f; }
#pragma unroll
    for (int i = 0; i < 6; ++i) m_sh[i] = 0.f;
#pragma unroll
    for (int i = 0; i < 4; ++i) { m_ch[i] = 0.f; m_rh[i] = 0.f; }

    const size_t TB = (size_t)TT * BB;
    float* const p_mco = out;
    float* const p_sch = out + TB * 3;
    float* const p_mro = out + TB * 19;
    float* const p_srh = out + TB * 20;
    float* const p_ssh = out + TB * 36;
    float* const p_sec = out + TB * 60;
    float* const p_ser = out + TB * 68;

#pragma unroll 1
    for (int t = 0; t < TT; ++t) {
        const size_t r = (size_t)t * BB + e;

        const float2* xp = (const float2*)(x + r * 6);
        const float2 a0 = xp[0], a1 = xp[1], a2 = xp[2];
        // padded to 8 with exact zeros (fmaf(0,0,acc)==acc exactly)
        const float xv[8] = {a0.x, a0.y, a1.x, a1.y, a2.x, a2.y, 0.f, 0.f};

        // ---- encoders: 2 ec + 2 er rows (ascending i, bit-exact) ----
        float s_ec[2], s_er[2];
#pragma unroll
        for (int k = 0; k < 2; ++k) {
            float acc = 0.f;
#pragma unroll
            for (int j = 0; j < 2; ++j) {
                const float4 w = sm.ecI[k][j][role];
                acc = fmaf(xv[4 * j + 0], w.x, acc);
                acc = fmaf(xv[4 * j + 1], w.y, acc);
                acc = fmaf(xv[4 * j + 2], w.z, acc);
                acc = fmaf(xv[4 * j + 3], w.w, acc);
            }
            s_ec[k] = lif(acc + b_ec[k], m_ec[k]);
        }
#pragma unroll
        for (int k = 0; k < 2; ++k) {
            float acc = 0.f;
#pragma unroll
            for (int j = 0; j < 2; ++j) {
                const float4 w = sm.erI[k][j][role];
                acc = fmaf(xv[4 * j + 0], w.x, acc);
                acc = fmaf(xv[4 * j + 1], w.y, acc);
                acc = fmaf(xv[4 * j + 2], w.z, acc);
                acc = fmaf(xv[4 * j + 3], w.w, acc);
            }
            s_er[k] = lif(acc + b_er[k], m_er[k]);
        }
        // publish enc spikes
        *(float2*)(sb + eo)     = make_float2(s_ec[0], s_ec[1]);
        *(float2*)(sb + 8 + eo) = make_float2(s_er[0], s_er[1]);
        __syncwarp();

        // ---- shared layer: 6 rows over ein[16] (concat order, ascending) ----
        const float4* einp = (const float4*)sb;
        const float4 e0 = einp[0], e1 = einp[1], e2 = einp[2], e3 = einp[3];
        const float ein[16] = {e0.x, e0.y, e0.z, e0.w, e1.x, e1.y, e1.z, e1.w,
                               e2.x, e2.y, e2.z, e2.w, e3.x, e3.y, e3.z, e3.w};
        float s_sh[6];
#pragma unroll
        for (int k = 0; k < 6; ++k) {
            float acc = 0.f;
#pragma unroll
            for (int j = 0; j < 4; ++j) {
                const float4 w = sm.sI[k][j][role];
                acc = fmaf(ein[4 * j + 0], w.x, acc);
                acc = fmaf(ein[4 * j + 1], w.y, acc);
                acc = fmaf(ein[4 * j + 2], w.z, acc);
                acc = fmaf(ein[4 * j + 3], w.w, acc);
            }
            s_sh[k] = lif(acc + b_sh[k], m_sh[k]);
        }
        *(float2*)(sb + 16 + so)     = make_float2(s_sh[0], s_sh[1]);
        *(float2*)(sb + 16 + so + 2) = make_float2(s_sh[2], s_sh[3]);
        *(float2*)(sb + 16 + so + 4) = make_float2(s_sh[4], s_sh[5]);
        __syncwarp();

        // ---- heads read shin[24] ----
        const float4* shp = (const float4*)(sb + 16);
        const float4 h0 = shp[0], h1 = shp[1], h2 = shp[2],
                     h3 = shp[3], h4 = shp[4], h5 = shp[5];
        const float shin[24] = {h0.x, h0.y, h0.z, h0.w, h1.x, h1.y, h1.z, h1.w,
                                h2.x, h2.y, h2.z, h2.w, h3.x, h3.y, h3.z, h3.w,
                                h4.x, h4.y, h4.z, h4.w, h5.x, h5.y, h5.z, h5.w};

        // classification hidden: 4 rows (ascending)
        float s_ch[4];
#pragma unroll
        for (int k = 0; k < 4; ++k) {
            float acc = 0.f;
#pragma unroll
            for (int j = 0; j < 6; ++j) {
                const float4 w = sm.chI[k][j][role];
                acc = fmaf(shin[4 * j + 0], w.x, acc);
                acc = fmaf(shin[4 * j + 1], w.y, acc);
                acc = fmaf(shin[4 * j + 2], w.z, acc);
                acc = fmaf(shin[4 * j + 3], w.w, acc);
            }
            s_ch[k] = lif(acc + b_ch[k], m_ch[k]);
        }

        // regression hidden: 4 rows, butterfly tree (bit-exact; pad-zero adds
        // skipped — only affect -0/+0 on dead intermediates)
        float s_rh[4];
#pragma unroll
        for (int k = 0; k < 4; ++k) {
            float p[24];
#pragma unroll
            for (int j = 0; j < 6; ++j) {
                const float4 w = sm.rhI[k][j][role];
                p[4 * j + 0] = shin[4 * j + 0] * w.x;
                p[4 * j + 1] = shin[4 * j + 1] * w.y;
                p[4 * j + 2] = shin[4 * j + 2] * w.z;
                p[4 * j + 3] = shin[4 * j + 3] * w.w;
            }
#pragma unroll
            for (int i = 0; i < 8; ++i) p[i] = p[i] + p[i + 16];
#pragma unroll
            for (int i = 0; i < 8; ++i) p[i] = p[i] + p[i + 8];
#pragma unroll
            for (int i = 0; i < 4; ++i) p[i] = p[i] + p[i + 4];
#pragma unroll
            for (int i = 0; i < 2; ++i) p[i] = p[i] + p[i + 2];
            s_rh[k] = lif(p[0] + p[1] + b_rh[k], m_rh[k]);
        }
        *(float4*)(sb + 40 + ho) = make_float4(s_ch[0], s_ch[1], s_ch[2], s_ch[3]);
        *(float4*)(sb + 56 + ho) = make_float4(s_rh[0], s_rh[1], s_rh[2], s_rh[3]);
        __syncwarp();

        // ---- output tail: roles 0-2 -> Wco rows, role 3 -> Wro ----
        {
            float acc = 0.f;
#pragma unroll
            for (int j = 0; j < 4; ++j) {
                const float4 s = tin[j];
                const float4 w = sm.tI[j][role];
                acc = fmaf(s.x, w.x, acc);
                acc = fmaf(s.y, w.y, acc);
                acc = fmaf(s.z, w.z, acc);
                acc = fmaf(s.w, w.w, acc);
            }
            lif(acc + btail, m_tail);
        }

        // ---- global stores (each thread stores what it owns) ----
        if (role < 3) p_mco[r * 3 + role] = m_tail;
        else          p_mro[r] = m_tail;
        *(float4*)(p_sch + r * 16 + ho) = make_float4(s_ch[0], s_ch[1], s_ch[2], s_ch[3]);
        *(float4*)(p_srh + r * 16 + ho) = make_float4(s_rh[0], s_rh[1], s_rh[2], s_rh[3]);
        {
            float2* q = (float2*)(p_ssh + r * 24 + so);
            q[0] = make_float2(s_sh[0], s_sh[1]);
            q[1] = make_float2(s_sh[2], s_sh[3]);
            q[2] = make_float2(s_sh[4], s_sh[5]);
        }
        *(float2*)(p_sec + r * 8 + eo) = make_float2(s_ec[0], s_ec[1]);
        *(float2*)(p_ser + r * 8 + eo) = make_float2(s_er[0], s_er[1]);
    }
}

extern "C" void kernel_launch(void* const* d_in, const int* in_sizes, int n_in,
                              void* d_out, int out_size)
{
    snn_kernel<<<128, 512>>>(
        (const float*)d_in[0],
        (const float*)d_in[1],  (const float*)d_in[2],
        (const float*)d_in[3],  (const float*)d_in[4],
        (const float*)d_in[5],  (const float*)d_in[6],
        (const float*)d_in[7],  (const float*)d_in[8],
        (const float*)d_in[9],  (const float*)d_in[10],
        (const float*)d_in[11], (const float*)d_in[12],
        (const float*)d_in[13], (const float*)d_in[14],
        (float*)d_out);
}

// round 11
// speedup vs baseline: 1.6515x; 1.1322x over previous
#include <cuda_runtime.h>

#define TT 100
#define BB 16384

// Interleaved weights: [k][j][role] -> the 4 roles of a warp hit 4 CONSECUTIVE
// float4s inside one LDS.128 window (64B) -> conflict-free.
// sp: per-element spike buffer, row stride 76 floats -> row banks = 12*row mod 32,
// distinct across the 8 subs of a warp -> conflict-free float4 access.
// Row layout: ec[0:8) er[8:16) sh[16:40) ch[40:56) rh[56:72)
struct Smem {
    float4 ecI[2][2][4];
    float4 erI[2][2][4];
    float4 sI [6][4][4];
    float4 chI[4][6][4];
    float4 rhI[4][6][4];
    float4 tI [4][4];      // roles 0-2 -> Wco rows, role 3 -> Wro
    float  sp[128][76];
    float  bec[8], ber[8], bs[24], bch[16], bco[3], brh[16], bro[1];
};

// snntorch Leaky, reset='subtract', THR=1, BETA=0.9 — bit-exact vs reference.
__device__ __forceinline__ float lif(float cur, float& m) {
    float mold = m;
    m = fmaf(0.9f, m, cur);
    if (mold > 1.0f) m -= 1.0f;
    return (m > 1.0f) ? 1.0f : 0.0f;
}

__global__ void __launch_bounds__(256)
snn_kernel(const float* __restrict__ x,
           const float* __restrict__ We_c, const float* __restrict__ be_c,
           const float* __restrict__ We_r, const float* __restrict__ be_r,
           const float* __restrict__ Wsp,  const float* __restrict__ bsp,
           const float* __restrict__ Wchp, const float* __restrict__ bchp,
           const float* __restrict__ Wcop, const float* __restrict__ bcop,
           const float* __restrict__ Wrhp, const float* __restrict__ brhp,
           const float* __restrict__ Wrop, const float* __restrict__ brop,
           float* __restrict__ out)
{
    __shared__ __align__(16) Smem sm;
    const int tid = threadIdx.x;

    // ---- staging: permute weights into interleaved layout ----
    for (int idx = tid; idx < 64; idx += 256) {          // ecI / erI
        int c = idx & 3, role = (idx >> 2) & 3, j = (idx >> 4) & 1, k = idx >> 5;
        int col = 4 * j + c, row = 2 * role + k;
        ((float*)sm.ecI)[idx] = (col < 6) ? We_c[row * 6 + col] : 0.f;
        ((float*)sm.erI)[idx] = (col < 6) ? We_r[row * 6 + col] : 0.f;
    }
    for (int idx = tid; idx < 384; idx += 256) {         // sI
        int c = idx & 3, role = (idx >> 2) & 3, j = (idx >> 4) & 3, k = idx >> 6;
        ((float*)sm.sI)[idx] = Wsp[(6 * role + k) * 16 + 4 * j + c];
    }
    for (int idx = tid; idx < 384; idx += 256) {         // chI / rhI
        int c = idx & 3, role = (idx >> 2) & 3, jk = idx >> 4;
        int j = jk % 6, k = jk / 6, off = (4 * role + k) * 24 + 4 * j + c;
        ((float*)sm.chI)[idx] = Wchp[off];
        ((float*)sm.rhI)[idx] = Wrhp[off];
    }
    for (int idx = tid; idx < 64; idx += 256) {          // tI
        int c = idx & 3, role = (idx >> 2) & 3, j = idx >> 4;
        ((float*)sm.tI)[idx] = (role < 3) ? Wcop[role * 16 + 4 * j + c]
                                          : Wrop[4 * j + c];
    }
    if (tid < 8)  { sm.bec[tid] = be_c[tid]; sm.ber[tid] = be_r[tid]; }
    if (tid < 24) sm.bs[tid]  = bsp[tid];
    if (tid < 16) { sm.bch[tid] = bchp[tid]; sm.brh[tid] = brhp[tid]; }
    if (tid < 3)  sm.bco[tid] = bcop[tid];
    if (tid == 0) sm.bro[0] = brop[0];
    __syncthreads();

    // ---- 4-way role split, 2 elements per thread ----
    const int lane = tid & 31;
    const int warp = tid >> 5;           // 0..7
    const int role = lane >> 3;          // 0..3
    const int sub  = lane & 7;
    const int elemA = warp * 16 + sub;   // block-local elements
    const int elemB = elemA + 8;
    const int eA = blockIdx.x * 128 + elemA;

    const int eo = role * 2;
    const int so = role * 6;
    const int ho = role * 4;

    float* const sbA = &sm.sp[elemA][0];
    float* const sbB = &sm.sp[elemB][0];

    // biases -> registers (shared by both elements)
    float b_ec[2], b_er[2], b_sh[6], b_ch[4], b_rh[4];
#pragma unroll
    for (int k = 0; k < 2; ++k) { b_ec[k] = sm.bec[eo + k]; b_er[k] = sm.ber[eo + k]; }
#pragma unroll
    for (int k = 0; k < 6; ++k) b_sh[k] = sm.bs[so + k];
#pragma unroll
    for (int k = 0; k < 4; ++k) { b_ch[k] = sm.bch[ho + k]; b_rh[k] = sm.brh[ho + k]; }
    const float btail = (role < 3) ? sm.bco[role] : sm.bro[0];
    const int toff = (role < 3) ? 40 : 56;

    // membranes, per element
    float m_ec[2][2], m_er[2][2], m_sh[2][6], m_ch[2][4], m_rh[2][4], m_tail[2];
#pragma unroll
    for (int u = 0; u < 2; ++u) {
#pragma unroll
        for (int i = 0; i < 2; ++i) { m_ec[u][i] = 0.f; m_er[u][i] = 0.f; }
#pragma unroll
        for (int i = 0; i < 6; ++i) m_sh[u][i] = 0.f;
#pragma unroll
        for (int i = 0; i < 4; ++i) { m_ch[u][i] = 0.f; m_rh[u][i] = 0.f; }
        m_tail[u] = 0.f;
    }

    const size_t TB = (size_t)TT * BB;
    float* const p_mco = out;
    float* const p_sch = out + TB * 3;
    float* const p_mro = out + TB * 19;
    float* const p_srh = out + TB * 20;
    float* const p_ssh = out + TB * 36;
    float* const p_sec = out + TB * 60;
    float* const p_ser = out + TB * 68;

#pragma unroll 1
    for (int t = 0; t < TT; ++t) {
        const size_t rA = (size_t)t * BB + eA;
        const size_t rB = rA + 8;

        float xv[2][8];
#pragma unroll
        for (int u = 0; u < 2; ++u) {
            const float2* xp = (const float2*)(x + (u ? rB : rA) * 6);
            const float2 a0 = xp[0], a1 = xp[1], a2 = xp[2];
            xv[u][0] = a0.x; xv[u][1] = a0.y; xv[u][2] = a1.x; xv[u][3] = a1.y;
            xv[u][4] = a2.x; xv[u][5] = a2.y; xv[u][6] = 0.f;  xv[u][7] = 0.f;
        }

        // ---- encoders: weight loaded once, used for both elements ----
        float s_ec[2][2], s_er[2][2];
#pragma unroll
        for (int k = 0; k < 2; ++k) {
            float accA = 0.f, accB = 0.f;
#pragma unroll
            for (int j = 0; j < 2; ++j) {
                const float4 w = sm.ecI[k][j][role];
                accA = fmaf(xv[0][4*j+0], w.x, accA); accB = fmaf(xv[1][4*j+0], w.x, accB);
                accA = fmaf(xv[0][4*j+1], w.y, accA); accB = fmaf(xv[1][4*j+1], w.y, accB);
                accA = fmaf(xv[0][4*j+2], w.z, accA); accB = fmaf(xv[1][4*j+2], w.z, accB);
                accA = fmaf(xv[0][4*j+3], w.w, accA); accB = fmaf(xv[1][4*j+3], w.w, accB);
            }
            s_ec[0][k] = lif(accA + b_ec[k], m_ec[0][k]);
            s_ec[1][k] = lif(accB + b_ec[k], m_ec[1][k]);
        }
#pragma unroll
        for (int k = 0; k < 2; ++k) {
            float accA = 0.f, accB = 0.f;
#pragma unroll
            for (int j = 0; j < 2; ++j) {
                const float4 w = sm.erI[k][j][role];
                accA = fmaf(xv[0][4*j+0], w.x, accA); accB = fmaf(xv[1][4*j+0], w.x, accB);
                accA = fmaf(xv[0][4*j+1], w.y, accA); accB = fmaf(xv[1][4*j+1], w.y, accB);
                accA = fmaf(xv[0][4*j+2], w.z, accA); accB = fmaf(xv[1][4*j+2], w.z, accB);
                accA = fmaf(xv[0][4*j+3], w.w, accA); accB = fmaf(xv[1][4*j+3], w.w, accB);
            }
            s_er[0][k] = lif(accA + b_er[k], m_er[0][k]);
            s_er[1][k] = lif(accB + b_er[k], m_er[1][k]);
        }
        *(float2*)(sbA + eo)     = make_float2(s_ec[0][0], s_ec[0][1]);
        *(float2*)(sbA + 8 + eo) = make_float2(s_er[0][0], s_er[0][1]);
        *(float2*)(sbB + eo)     = make_float2(s_ec[1][0], s_ec[1][1]);
        *(float2*)(sbB + 8 + eo) = make_float2(s_er[1][0], s_er[1][1]);
        __syncwarp();

        // ---- shared layer ----
        float ein[2][16];
#pragma unroll
        for (int u = 0; u < 2; ++u) {
            const float4* p4 = (const float4*)(u ? sbB : sbA);
#pragma unroll
            for (int j = 0; j < 4; ++j) {
                const float4 v = p4[j];
                ein[u][4*j+0] = v.x; ein[u][4*j+1] = v.y;
                ein[u][4*j+2] = v.z; ein[u][4*j+3] = v.w;
            }
        }
        float s_sh[2][6];
#pragma unroll
        for (int k = 0; k < 6; ++k) {
            float accA = 0.f, accB = 0.f;
#pragma unroll
            for (int j = 0; j < 4; ++j) {
                const float4 w = sm.sI[k][j][role];
                accA = fmaf(ein[0][4*j+0], w.x, accA); accB = fmaf(ein[1][4*j+0], w.x, accB);
                accA = fmaf(ein[0][4*j+1], w.y, accA); accB = fmaf(ein[1][4*j+1], w.y, accB);
                accA = fmaf(ein[0][4*j+2], w.z, accA); accB = fmaf(ein[1][4*j+2], w.z, accB);
                accA = fmaf(ein[0][4*j+3], w.w, accA); accB = fmaf(ein[1][4*j+3], w.w, accB);
            }
            s_sh[0][k] = lif(accA + b_sh[k], m_sh[0][k]);
            s_sh[1][k] = lif(accB + b_sh[k], m_sh[1][k]);
        }
#pragma unroll
        for (int u = 0; u < 2; ++u) {
            float* sb = u ? sbB : sbA;
            *(float2*)(sb + 16 + so)     = make_float2(s_sh[u][0], s_sh[u][1]);
            *(float2*)(sb + 16 + so + 2) = make_float2(s_sh[u][2], s_sh[u][3]);
            *(float2*)(sb + 16 + so + 4) = make_float2(s_sh[u][4], s_sh[u][5]);
        }
        __syncwarp();

        float shin[2][24];
#pragma unroll
        for (int u = 0; u < 2; ++u) {
            const float4* p4 = (const float4*)((u ? sbB : sbA) + 16);
#pragma unroll
            for (int j = 0; j < 6; ++j) {
                const float4 v = p4[j];
                shin[u][4*j+0] = v.x; shin[u][4*j+1] = v.y;
                shin[u][4*j+2] = v.z; shin[u][4*j+3] = v.w;
            }
        }

        // ---- classification hidden ----
        float s_ch[2][4];
#pragma unroll
        for (int k = 0; k < 4; ++k) {
            float accA = 0.f, accB = 0.f;
#pragma unroll
            for (int j = 0; j < 6; ++j) {
                const float4 w = sm.chI[k][j][role];
                accA = fmaf(shin[0][4*j+0], w.x, accA); accB = fmaf(shin[1][4*j+0], w.x, accB);
                accA = fmaf(shin[0][4*j+1], w.y, accA); accB = fmaf(shin[1][4*j+1], w.y, accB);
                accA = fmaf(shin[0][4*j+2], w.z, accA); accB = fmaf(shin[1][4*j+2], w.z, accB);
                accA = fmaf(shin[0][4*j+3], w.w, accA); accB = fmaf(shin[1][4*j+3], w.w, accB);
            }
            s_ch[0][k] = lif(accA + b_ch[k], m_ch[0][k]);
            s_ch[1][k] = lif(accB + b_ch[k], m_ch[1][k]);
        }

        // ---- regression hidden: butterfly tree per element (bit-exact) ----
        float s_rh[2][4];
#pragma unroll
        for (int k = 0; k < 4; ++k) {
            float w24[24];
#pragma unroll
            for (int j = 0; j < 6; ++j) {
                const float4 w = sm.rhI[k][j][role];
                w24[4*j+0] = w.x; w24[4*j+1] = w.y; w24[4*j+2] = w.z; w24[4*j+3] = w.w;
            }
#pragma unroll
            for (int u = 0; u < 2; ++u) {
                float p[24];
#pragma unroll
                for (int i = 0; i < 24; ++i) p[i] = shin[u][i] * w24[i];
#pragma unroll
                for (int i = 0; i < 8; ++i) p[i] = p[i] + p[i + 16];
#pragma unroll
                for (int i = 0; i < 8; ++i) p[i] = p[i] + p[i + 8];
#pragma unroll
                for (int i = 0; i < 4; ++i) p[i] = p[i] + p[i + 4];
#pragma unroll
                for (int i = 0; i < 2; ++i) p[i] = p[i] + p[i + 2];
                s_rh[u][k] = lif(p[0] + p[1] + b_rh[k], m_rh[u][k]);
            }
        }
#pragma unroll
        for (int u = 0; u < 2; ++u) {
            float* sb = u ? sbB : sbA;
            *(float4*)(sb + 40 + ho) = make_float4(s_ch[u][0], s_ch[u][1], s_ch[u][2], s_ch[u][3]);
            *(float4*)(sb + 56 + ho) = make_float4(s_rh[u][0], s_rh[u][1], s_rh[u][2], s_rh[u][3]);
        }
        __syncwarp();

        // ---- output tail ----
#pragma unroll
        for (int u = 0; u < 2; ++u) {
            const float4* tin = (const float4*)((u ? sbB : sbA) + toff);
            float acc = 0.f;
#pragma unroll
            for (int j = 0; j < 4; ++j) {
                const float4 s = tin[j];
                const float4 w = sm.tI[j][role];
                acc = fmaf(s.x, w.x, acc);
                acc = fmaf(s.y, w.y, acc);
                acc = fmaf(s.z, w.z, acc);
                acc = fmaf(s.w, w.w, acc);
            }
            lif(acc + btail, m_tail[u]);
        }

        // ---- global stores ----
#pragma unroll
        for (int u = 0; u < 2; ++u) {
            const size_t r = u ? rB : rA;
            if (role < 3) p_mco[r * 3 + role] = m_tail[u];
            else          p_mro[r] = m_tail[u];
            *(float4*)(p_sch + r * 16 + ho) = make_float4(s_ch[u][0], s_ch[u][1], s_ch[u][2], s_ch[u][3]);
            *(float4*)(p_srh + r * 16 + ho) = make_float4(s_rh[u][0], s_rh[u][1], s_rh[u][2], s_rh[u][3]);
            float2* q = (float2*)(p_ssh + r * 24 + so);
            q[0] = make_float2(s_sh[u][0], s_sh[u][1]);
            q[1] = make_float2(s_sh[u][2], s_sh[u][3]);
            q[2] = make_float2(s_sh[u][4], s_sh[u][5]);
            *(float2*)(p_sec + r * 8 + eo) = make_float2(s_ec[u][0], s_ec[u][1]);
            *(float2*)(p_ser + r * 8 + eo) = make_float2(s_er[u][0], s_er[u][1]);
        }
    }
}

extern "C" void kernel_launch(void* const* d_in, const int* in_sizes, int n_in,
                              void* d_out, int out_size)
{
    snn_kernel<<<128, 256>>>(
        (const float*)d_in[0],
        (const float*)d_in[1],  (const float*)d_in[2],
        (const float*)d_in[3],  (const float*)d_in[4],
        (const float*)d_in[5],  (const float*)d_in[6],
        (const float*)d_in[7],  (const float*)d_in[8],
        (const float*)d_in[9],  (const float*)d_in[10],
        (const float*)d_in[11], (const float*)d_in[12],
        (const float*)d_in[13], (const float*)d_in[14],
        (float*)d_out);
}